// round 7
// baseline (speedup 1.0000x reference)
#include <cuda_runtime.h>
#include <cuda_fp16.h>

// Fisher-Kolmogorov rollout. R7 = R2's flat max-occupancy kernel (proven to
// run at the LTS cap: 85% occ, 11.8 TB/s effective) with the two fp32 D/rho
// reads replaced by one packed half2 {D,rho} read (validated rel_err ~3e-5).
// Effective L2 traffic per step: 64 MB -> 40 MB.

#define W        128
#define BATCH    2
#define SUBSTEPS 10
#define MAX_DAYS 4
#define NSTEPS   (SUBSTEPS * MAX_DAYS)
#define MICRO_DT 0.1f

#define VOL  ((size_t)W * W * W)
#define NTOT (BATCH * VOL)

__device__ float g_buf0[NTOT];
__device__ float g_buf1[NTOT];
__device__ __half2 g_dr[NTOT];          // {D, rho} per point, 16 MB

struct __align__(16) H24 { __half2 h[4]; };

__device__ __forceinline__ float4 f4ld(const float* p) {
    return *reinterpret_cast<const float4*>(p);
}

// Pack D,rho -> half2 (one-time; runs inside the graph, deterministic).
__global__ __launch_bounds__(256)
void prep_dr(const float* __restrict__ D, const float* __restrict__ R,
             __half2* __restrict__ dr)
{
    const size_t i = ((size_t)blockIdx.x * 256 + threadIdx.x) * 4;
    float4 d = f4ld(D + i);
    float4 r = f4ld(R + i);
    H24 q;
    q.h[0] = __floats2half2_rn(d.x, r.x);
    q.h[1] = __floats2half2_rn(d.y, r.y);
    q.h[2] = __floats2half2_rn(d.z, r.z);
    q.h[3] = __floats2half2_rn(d.w, r.w);
    *reinterpret_cast<H24*>(dr + i) = q;
}

__device__ __forceinline__ void fk_comp(float& o, float c, float nb2,
                                        float nb4, __half2 drh)
{
    const float2 d2 = __half22float2(drh);        // x=D, y=rho
    const float lap = nb2 + nb4 - 6.0f * c;
    o = c + MICRO_DT * (d2.x * lap + d2.y * c * (1.0f - c));
}

__global__ __launch_bounds__(512)
void fk_step(const float* __restrict__ usrc,
             float* __restrict__ udst,
             float* __restrict__ uout,
             const __half2* __restrict__ dr,
             const int* __restrict__ dt_days,
             int day, int sub)
{
    const int b  = blockIdx.z >> 5;                        // 0..1
    const int dt = __ldg(dt_days + b);
    if (day >= dt) return;                                  // inactive: no work

    const bool fin = (day == dt - 1) && (sub == SUBSTEPS - 1);

    const int x4 = threadIdx.x << 2;                       // 0..124
    const int y  = blockIdx.y * 4 + threadIdx.y;           // 0..127
    const int z  = (blockIdx.z & 31) * 4 + threadIdx.z;    // 0..127

    const size_t base = (((size_t)b * W + z) * W + y) * W + x4;
    const size_t PL = (size_t)W * W;

    const float4 c = f4ld(usrc + base);

    const float left  = (x4 == 0)     ? 0.0f : __ldg(usrc + base - 1);
    const float right = (x4 == W - 4) ? 0.0f : __ldg(usrc + base + 4);

    const float4 zero4 = make_float4(0.f, 0.f, 0.f, 0.f);
    const float4 ym = (y == 0)     ? zero4 : f4ld(usrc + base - W);
    const float4 yp = (y == W - 1) ? zero4 : f4ld(usrc + base + W);
    const float4 zm = (z == 0)     ? zero4 : f4ld(usrc + base - PL);
    const float4 zp = (z == W - 1) ? zero4 : f4ld(usrc + base + PL);

    const H24 q = *reinterpret_cast<const H24*>(dr + base);

    float4 o;
    fk_comp(o.x, c.x, left + c.y, ym.x + yp.x + zm.x + zp.x, q.h[0]);
    fk_comp(o.y, c.y, c.x  + c.z, ym.y + yp.y + zm.y + zp.y, q.h[1]);
    fk_comp(o.z, c.z, c.y  + c.w, ym.z + yp.z + zm.z + zp.z, q.h[2]);
    fk_comp(o.w, c.w, c.z + right, ym.w + yp.w + zm.w + zp.w, q.h[3]);

    if (fin) {
        o.x = fminf(fmaxf(o.x, 0.0f), 1.0f);
        o.y = fminf(fmaxf(o.y, 0.0f), 1.0f);
        o.z = fminf(fmaxf(o.z, 0.0f), 1.0f);
        o.w = fminf(fmaxf(o.w, 0.0f), 1.0f);
        *reinterpret_cast<float4*>(uout + base) = o;
    } else {
        *reinterpret_cast<float4*>(udst + base) = o;
    }
}

// Handles dt_days[b] == 0 batches: clipped copy of u_t0 into d_out.
__global__ __launch_bounds__(512)
void fk_tail(const float* __restrict__ u0,
             float* __restrict__ out,
             const int* __restrict__ dt_days)
{
    const int b = blockIdx.z >> 5;
    if (__ldg(dt_days + b) != 0) return;

    const int x4 = threadIdx.x << 2;
    const int y  = blockIdx.y * 4 + threadIdx.y;
    const int z  = (blockIdx.z & 31) * 4 + threadIdx.z;
    const size_t base = (((size_t)b * W + z) * W + y) * W + x4;

    float4 v = f4ld(u0 + base);
    v.x = fminf(fmaxf(v.x, 0.0f), 1.0f);
    v.y = fminf(fmaxf(v.y, 0.0f), 1.0f);
    v.z = fminf(fmaxf(v.z, 0.0f), 1.0f);
    v.w = fminf(fmaxf(v.w, 0.0f), 1.0f);
    *reinterpret_cast<float4*>(out + base) = v;
}

extern "C" void kernel_launch(void* const* d_in, const int* in_sizes, int n_in,
                              void* d_out, int out_size)
{
    const float* u_t0    = (const float*)d_in[0];
    const float* D_map   = (const float*)d_in[1];
    const float* rho_map = (const float*)d_in[2];
    const int*   dt_days = (const int*)  d_in[3];
    float*       out     = (float*)d_out;

    float *p0 = nullptr, *p1 = nullptr;
    __half2* dr = nullptr;
    cudaGetSymbolAddress((void**)&p0, g_buf0);
    cudaGetSymbolAddress((void**)&p1, g_buf1);
    cudaGetSymbolAddress((void**)&dr, g_dr);
    float* bufs[2] = { p0, p1 };

    // One-time D/rho packing (inside the graph; deterministic).
    prep_dr<<<(unsigned)(NTOT / 4 / 256), 256>>>(D_map, rho_map, dr);

    dim3 block(32, 4, 4);                         // 512 threads
    dim3 grid(1, W / 4, (W / 4) * BATCH);         // 2048 blocks

    for (int s = 0; s < NSTEPS; ++s) {
        const float* src = (s == 0) ? u_t0 : bufs[s & 1];
        float*       dst = bufs[(s + 1) & 1];
        fk_step<<<grid, block>>>(src, dst, out, dr, dt_days,
                                 s / SUBSTEPS, s % SUBSTEPS);
    }

    dim3 tblock(32, 4, 4);
    dim3 tgrid(1, W / 4, (W / 4) * BATCH);
    fk_tail<<<tgrid, tblock>>>(u_t0, out, dt_days);

    (void)in_sizes; (void)n_in; (void)out_size;
}

// round 8
// speedup vs baseline: 1.1294x; 1.1294x over previous
#include <cuda_runtime.h>
#include <cuda_fp16.h>

// Fisher-Kolmogorov rollout. R8: z-pair ILP kernel — each thread produces two
// z-adjacent float4 outputs. 10 independent vector loads per thread (MLP~10),
// shfl x-halo (no scalar LDGs), packed half2 {D,rho}. 512K threads.

#define W        128
#define BATCH    2
#define SUBSTEPS 10
#define MAX_DAYS 4
#define NSTEPS   (SUBSTEPS * MAX_DAYS)
#define MICRO_DT 0.1f

#define VOL  ((size_t)W * W * W)
#define NTOT (BATCH * VOL)

__device__ float g_buf0[NTOT];
__device__ float g_buf1[NTOT];
__device__ __half2 g_dr[NTOT];          // {D, rho} per point, 16 MB

struct __align__(16) H24 { __half2 h[4]; };

__device__ __forceinline__ float4 f4ld(const float* p) {
    return *reinterpret_cast<const float4*>(p);
}

// Pack D,rho -> half2 (one-time per replay; deterministic).
__global__ __launch_bounds__(256)
void prep_dr(const float* __restrict__ D, const float* __restrict__ R,
             __half2* __restrict__ dr)
{
    const size_t i = ((size_t)blockIdx.x * 256 + threadIdx.x) * 4;
    float4 d = f4ld(D + i);
    float4 r = f4ld(R + i);
    H24 q;
    q.h[0] = __floats2half2_rn(d.x, r.x);
    q.h[1] = __floats2half2_rn(d.y, r.y);
    q.h[2] = __floats2half2_rn(d.z, r.z);
    q.h[3] = __floats2half2_rn(d.w, r.w);
    *reinterpret_cast<H24*>(dr + i) = q;
}

__device__ __forceinline__ void fk_comp(float& o, float c, float nb2,
                                        float nb4, __half2 drh)
{
    const float2 d2 = __half22float2(drh);        // x=D, y=rho
    const float lap = nb2 + nb4 - 6.0f * c;
    o = c + MICRO_DT * (d2.x * lap + d2.y * c * (1.0f - c));
}

__device__ __forceinline__ float4 fk_point(float4 c, float4 ym, float4 yp,
                                           float4 zm, float4 zp,
                                           float lf, float rt, H24 q)
{
    float4 o;
    fk_comp(o.x, c.x, lf  + c.y, ym.x + yp.x + zm.x + zp.x, q.h[0]);
    fk_comp(o.y, c.y, c.x + c.z, ym.y + yp.y + zm.y + zp.y, q.h[1]);
    fk_comp(o.z, c.z, c.y + c.w, ym.z + yp.z + zm.z + zp.z, q.h[2]);
    fk_comp(o.w, c.w, c.z + rt,  ym.w + yp.w + zm.w + zp.w, q.h[3]);
    return o;
}

__device__ __forceinline__ float4 clip01(float4 v)
{
    v.x = fminf(fmaxf(v.x, 0.f), 1.f);
    v.y = fminf(fmaxf(v.y, 0.f), 1.f);
    v.z = fminf(fmaxf(v.z, 0.f), 1.f);
    v.w = fminf(fmaxf(v.w, 0.f), 1.f);
    return v;
}

__global__ __launch_bounds__(512)
void fk_step(const float* __restrict__ usrc,
             float* __restrict__ udst,
             float* __restrict__ uout,
             const __half2* __restrict__ dr,
             const int* __restrict__ dt_days,
             int day, int sub)
{
    const int b  = blockIdx.z;
    const int dt = __ldg(dt_days + b);
    if (day >= dt) return;                              // block-uniform
    const bool fin = (day == dt - 1) && (sub == SUBSTEPS - 1);

    const int tx = threadIdx.x;                         // 0..31 (float4 lane)
    const int y  = blockIdx.y * 4 + threadIdx.y;        // 0..127
    const int z0 = (blockIdx.x * 4 + threadIdx.z) * 2;  // 0,2,..,126
    const int x4 = tx << 2;

    const size_t PL = (size_t)W * W;
    const size_t base = ((size_t)b * VOL) + (((size_t)z0 * W) + y) * W + x4;

    const float4 zero4 = make_float4(0.f, 0.f, 0.f, 0.f);

    // 10 independent vector loads (MLP ~ 10)
    const float4 um  = (z0 > 0)      ? f4ld(usrc + base - PL)      : zero4;
    const float4 u0  =                 f4ld(usrc + base);
    const float4 u1  =                 f4ld(usrc + base + PL);
    const float4 up  = (z0 < W - 2)  ? f4ld(usrc + base + 2 * PL)  : zero4;
    const float4 ym0 = (y > 0)       ? f4ld(usrc + base - W)       : zero4;
    const float4 yp0 = (y < W - 1)   ? f4ld(usrc + base + W)       : zero4;
    const float4 ym1 = (y > 0)       ? f4ld(usrc + base + PL - W)  : zero4;
    const float4 yp1 = (y < W - 1)   ? f4ld(usrc + base + PL + W)  : zero4;
    const H24 q0 = *reinterpret_cast<const H24*>(dr + base);
    const H24 q1 = *reinterpret_cast<const H24*>(dr + base + PL);

    // x-halo via shuffle (full warp = full x-row)
    float lf0 = __shfl_up_sync(0xffffffffu, u0.w, 1);
    float rt0 = __shfl_down_sync(0xffffffffu, u0.x, 1);
    float lf1 = __shfl_up_sync(0xffffffffu, u1.w, 1);
    float rt1 = __shfl_down_sync(0xffffffffu, u1.x, 1);
    if (tx == 0)  { lf0 = 0.f; lf1 = 0.f; }
    if (tx == 31) { rt0 = 0.f; rt1 = 0.f; }

    float4 o0 = fk_point(u0, ym0, yp0, um, u1, lf0, rt0, q0);
    float4 o1 = fk_point(u1, ym1, yp1, u0, up, lf1, rt1, q1);

    if (fin) {
        o0 = clip01(o0);
        o1 = clip01(o1);
        *reinterpret_cast<float4*>(uout + base)      = o0;
        *reinterpret_cast<float4*>(uout + base + PL) = o1;
    } else {
        *reinterpret_cast<float4*>(udst + base)      = o0;
        *reinterpret_cast<float4*>(udst + base + PL) = o1;
    }
}

// Handles dt_days[b] == 0 batches: clipped copy of u_t0 into d_out.
__global__ __launch_bounds__(512)
void fk_tail(const float* __restrict__ u0,
             float* __restrict__ out,
             const int* __restrict__ dt_days)
{
    const int b = blockIdx.z >> 5;
    if (__ldg(dt_days + b) != 0) return;

    const int x4 = threadIdx.x << 2;
    const int y  = blockIdx.y * 4 + threadIdx.y;
    const int z  = (blockIdx.z & 31) * 4 + threadIdx.z;
    const size_t base = (((size_t)b * W + z) * W + y) * W + x4;

    float4 v = f4ld(u0 + base);
    *reinterpret_cast<float4*>(out + base) = clip01(v);
}

extern "C" void kernel_launch(void* const* d_in, const int* in_sizes, int n_in,
                              void* d_out, int out_size)
{
    const float* u_t0    = (const float*)d_in[0];
    const float* D_map   = (const float*)d_in[1];
    const float* rho_map = (const float*)d_in[2];
    const int*   dt_days = (const int*)  d_in[3];
    float*       out     = (float*)d_out;

    float *p0 = nullptr, *p1 = nullptr;
    __half2* dr = nullptr;
    cudaGetSymbolAddress((void**)&p0, g_buf0);
    cudaGetSymbolAddress((void**)&p1, g_buf1);
    cudaGetSymbolAddress((void**)&dr, g_dr);
    float* bufs[2] = { p0, p1 };

    prep_dr<<<(unsigned)(NTOT / 4 / 256), 256>>>(D_map, rho_map, dr);

    dim3 block(32, 4, 4);                        // 512 threads
    dim3 grid(W / 8, W / 4, BATCH);              // (16, 32, 2) = 1024 blocks

    for (int s = 0; s < NSTEPS; ++s) {
        const float* src = (s == 0) ? u_t0 : bufs[s & 1];
        float*       dst = bufs[(s + 1) & 1];
        fk_step<<<grid, block>>>(src, dst, out, dr, dt_days,
                                 s / SUBSTEPS, s % SUBSTEPS);
    }

    dim3 tblock(32, 4, 4);
    dim3 tgrid(1, W / 4, (W / 4) * BATCH);
    fk_tail<<<tgrid, tblock>>>(u_t0, out, dt_days);

    (void)in_sizes; (void)n_in; (void)out_size;
}

// round 9
// speedup vs baseline: 1.3790x; 1.2211x over previous
#include <cuda_runtime.h>
#include <cuda_fp16.h>

// Fisher-Kolmogorov rollout. R9 = R8 body (z-pair, MLP~10, shfl x-halo,
// packed half2 {D,rho}) + PDL to hide launch gaps / empty steps, and fp16
// packing fused into step 0 (no separate prep kernel).

#define W        128
#define BATCH    2
#define SUBSTEPS 10
#define MAX_DAYS 4
#define NSTEPS   (SUBSTEPS * MAX_DAYS)
#define MICRO_DT 0.1f

#define VOL  ((size_t)W * W * W)
#define NTOT (BATCH * VOL)

__device__ float g_buf0[NTOT];
__device__ float g_buf1[NTOT];
__device__ __half2 g_dr[NTOT];          // {D, rho} per point, 16 MB

struct __align__(16) H24 { __half2 h[4]; };

__device__ __forceinline__ float4 f4ld(const float* p) {
    return *reinterpret_cast<const float4*>(p);
}

__device__ __forceinline__ void fk_comp(float& o, float c, float nb2,
                                        float nb4, __half2 drh)
{
    const float2 d2 = __half22float2(drh);        // x=D, y=rho
    const float lap = nb2 + nb4 - 6.0f * c;
    o = c + MICRO_DT * (d2.x * lap + d2.y * c * (1.0f - c));
}

__device__ __forceinline__ float4 fk_point(float4 c, float4 ym, float4 yp,
                                           float4 zm, float4 zp,
                                           float lf, float rt, H24 q)
{
    float4 o;
    fk_comp(o.x, c.x, lf  + c.y, ym.x + yp.x + zm.x + zp.x, q.h[0]);
    fk_comp(o.y, c.y, c.x + c.z, ym.y + yp.y + zm.y + zp.y, q.h[1]);
    fk_comp(o.z, c.z, c.y + c.w, ym.z + yp.z + zm.z + zp.z, q.h[2]);
    fk_comp(o.w, c.w, c.z + rt,  ym.w + yp.w + zm.w + zp.w, q.h[3]);
    return o;
}

__device__ __forceinline__ float4 clip01(float4 v)
{
    v.x = fminf(fmaxf(v.x, 0.f), 1.f);
    v.y = fminf(fmaxf(v.y, 0.f), 1.f);
    v.z = fminf(fmaxf(v.z, 0.f), 1.f);
    v.w = fminf(fmaxf(v.w, 0.f), 1.f);
    return v;
}

__device__ __forceinline__ H24 pack_dr(float4 d, float4 r)
{
    H24 q;
    q.h[0] = __floats2half2_rn(d.x, r.x);
    q.h[1] = __floats2half2_rn(d.y, r.y);
    q.h[2] = __floats2half2_rn(d.z, r.z);
    q.h[3] = __floats2half2_rn(d.w, r.w);
    return q;
}

// ---- step 0: reads fp32 D/rho, packs g_dr, computes micro-step 0 ----
__global__ __launch_bounds__(512)
void fk_step0(const float* __restrict__ usrc,
              float* __restrict__ udst,
              const float* __restrict__ Dm,
              const float* __restrict__ Rm,
              __half2* __restrict__ dr,
              const int* __restrict__ dt_days)
{
#if __CUDA_ARCH__ >= 900
    cudaTriggerProgrammaticLaunchCompletion();
#endif
    const int b  = blockIdx.z;
    const int dt = __ldg(dt_days + b);
    if (dt <= 0) return;                 // day 0 active iff dt>0; never "fin"

    const int tx = threadIdx.x;
    const int y  = blockIdx.y * 4 + threadIdx.y;
    const int z0 = (blockIdx.x * 4 + threadIdx.z) * 2;
    const int x4 = tx << 2;

    const size_t PL = (size_t)W * W;
    const size_t base = ((size_t)b * VOL) + (((size_t)z0 * W) + y) * W + x4;

    const float4 zero4 = make_float4(0.f, 0.f, 0.f, 0.f);

    const float4 um  = (z0 > 0)     ? f4ld(usrc + base - PL)     : zero4;
    const float4 u0  =                f4ld(usrc + base);
    const float4 u1  =                f4ld(usrc + base + PL);
    const float4 up  = (z0 < W - 2) ? f4ld(usrc + base + 2 * PL) : zero4;
    const float4 ym0 = (y > 0)      ? f4ld(usrc + base - W)      : zero4;
    const float4 yp0 = (y < W - 1)  ? f4ld(usrc + base + W)      : zero4;
    const float4 ym1 = (y > 0)      ? f4ld(usrc + base + PL - W) : zero4;
    const float4 yp1 = (y < W - 1)  ? f4ld(usrc + base + PL + W) : zero4;
    const float4 d0  = f4ld(Dm + base);
    const float4 r0  = f4ld(Rm + base);
    const float4 d1  = f4ld(Dm + base + PL);
    const float4 r1  = f4ld(Rm + base + PL);

    const H24 q0 = pack_dr(d0, r0);
    const H24 q1 = pack_dr(d1, r1);
    *reinterpret_cast<H24*>(dr + base)      = q0;
    *reinterpret_cast<H24*>(dr + base + PL) = q1;

    float lf0 = __shfl_up_sync(0xffffffffu, u0.w, 1);
    float rt0 = __shfl_down_sync(0xffffffffu, u0.x, 1);
    float lf1 = __shfl_up_sync(0xffffffffu, u1.w, 1);
    float rt1 = __shfl_down_sync(0xffffffffu, u1.x, 1);
    if (tx == 0)  { lf0 = 0.f; lf1 = 0.f; }
    if (tx == 31) { rt0 = 0.f; rt1 = 0.f; }

    const float4 o0 = fk_point(u0, ym0, yp0, um, u1, lf0, rt0, q0);
    const float4 o1 = fk_point(u1, ym1, yp1, u0, up, lf1, rt1, q1);

    *reinterpret_cast<float4*>(udst + base)      = o0;
    *reinterpret_cast<float4*>(udst + base + PL) = o1;
}

// ---- steps 1..39: R8 body + PDL trigger/gridsync ----
__global__ __launch_bounds__(512)
void fk_step(const float* __restrict__ usrc,
             float* __restrict__ udst,
             float* __restrict__ uout,
             const __half2* __restrict__ dr,
             const int* __restrict__ dt_days,
             int day, int sub)
{
#if __CUDA_ARCH__ >= 900
    cudaTriggerProgrammaticLaunchCompletion();
#endif
    const int b  = blockIdx.z;
    const int dt = __ldg(dt_days + b);   // never written by any kernel: safe pre-sync
    if (day >= dt) return;               // empty/inactive: overlap entirely
    const bool fin = (day == dt - 1) && (sub == SUBSTEPS - 1);

    const int tx = threadIdx.x;
    const int y  = blockIdx.y * 4 + threadIdx.y;
    const int z0 = (blockIdx.x * 4 + threadIdx.z) * 2;
    const int x4 = tx << 2;

    const size_t PL = (size_t)W * W;
    const size_t base = ((size_t)b * VOL) + (((size_t)z0 * W) + y) * W + x4;

#if __CUDA_ARCH__ >= 900
    cudaGridDependencySynchronize();      // all dependent loads/stores below
#endif

    const float4 zero4 = make_float4(0.f, 0.f, 0.f, 0.f);

    const float4 um  = (z0 > 0)     ? f4ld(usrc + base - PL)     : zero4;
    const float4 u0  =                f4ld(usrc + base);
    const float4 u1  =                f4ld(usrc + base + PL);
    const float4 up  = (z0 < W - 2) ? f4ld(usrc + base + 2 * PL) : zero4;
    const float4 ym0 = (y > 0)      ? f4ld(usrc + base - W)      : zero4;
    const float4 yp0 = (y < W - 1)  ? f4ld(usrc + base + W)      : zero4;
    const float4 ym1 = (y > 0)      ? f4ld(usrc + base + PL - W) : zero4;
    const float4 yp1 = (y < W - 1)  ? f4ld(usrc + base + PL + W) : zero4;
    const H24 q0 = *reinterpret_cast<const H24*>(dr + base);
    const H24 q1 = *reinterpret_cast<const H24*>(dr + base + PL);

    float lf0 = __shfl_up_sync(0xffffffffu, u0.w, 1);
    float rt0 = __shfl_down_sync(0xffffffffu, u0.x, 1);
    float lf1 = __shfl_up_sync(0xffffffffu, u1.w, 1);
    float rt1 = __shfl_down_sync(0xffffffffu, u1.x, 1);
    if (tx == 0)  { lf0 = 0.f; lf1 = 0.f; }
    if (tx == 31) { rt0 = 0.f; rt1 = 0.f; }

    float4 o0 = fk_point(u0, ym0, yp0, um, u1, lf0, rt0, q0);
    float4 o1 = fk_point(u1, ym1, yp1, u0, up, lf1, rt1, q1);

    if (fin) {
        o0 = clip01(o0);
        o1 = clip01(o1);
        *reinterpret_cast<float4*>(uout + base)      = o0;
        *reinterpret_cast<float4*>(uout + base + PL) = o1;
    } else {
        *reinterpret_cast<float4*>(udst + base)      = o0;
        *reinterpret_cast<float4*>(udst + base + PL) = o1;
    }
}

// dt==0 batches: clipped copy of u_t0 -> d_out. Independent of all steps
// (reads only u_t0; writes a disjoint out region) -> no gridsync.
__global__ __launch_bounds__(512)
void fk_tail(const float* __restrict__ u0,
             float* __restrict__ out,
             const int* __restrict__ dt_days)
{
#if __CUDA_ARCH__ >= 900
    cudaTriggerProgrammaticLaunchCompletion();
#endif
    const int b = blockIdx.z >> 5;
    if (__ldg(dt_days + b) != 0) return;

    const int x4 = threadIdx.x << 2;
    const int y  = blockIdx.y * 4 + threadIdx.y;
    const int z  = (blockIdx.z & 31) * 4 + threadIdx.z;
    const size_t base = (((size_t)b * W + z) * W + y) * W + x4;

    float4 v = f4ld(u0 + base);
    *reinterpret_cast<float4*>(out + base) = clip01(v);
}

extern "C" void kernel_launch(void* const* d_in, const int* in_sizes, int n_in,
                              void* d_out, int out_size)
{
    const float* u_t0    = (const float*)d_in[0];
    const float* D_map   = (const float*)d_in[1];
    const float* rho_map = (const float*)d_in[2];
    const int*   dt_days = (const int*)  d_in[3];
    float*       out     = (float*)d_out;

    float *p0 = nullptr, *p1 = nullptr;
    __half2* dr = nullptr;
    cudaGetSymbolAddress((void**)&p0, g_buf0);
    cudaGetSymbolAddress((void**)&p1, g_buf1);
    cudaGetSymbolAddress((void**)&dr, g_dr);
    float* bufs[2] = { p0, p1 };

    dim3 block(32, 4, 4);                        // 512 threads
    dim3 grid(W / 8, W / 4, BATCH);              // (16, 32, 2) = 1024 blocks

    cudaLaunchAttribute attrs[1];
    attrs[0].id = cudaLaunchAttributeProgrammaticStreamSerialization;
    attrs[0].val.programmaticStreamSerializationAllowed = 1;

    cudaLaunchConfig_t cfg = {};
    cfg.gridDim = grid;
    cfg.blockDim = block;
    cfg.dynamicSmemBytes = 0;
    cfg.stream = 0;                               // legacy default stream (captured)
    cfg.attrs = attrs;
    cfg.numAttrs = 1;

    // Step 0: fused fp16 packing + first micro-step.
    cudaLaunchKernelEx(&cfg, fk_step0, u_t0, bufs[1], D_map, rho_map,
                       (__half2*)dr, dt_days);

    // Steps 1..39 (ping-pong; step s reads bufs[s&1], writes bufs[(s+1)&1]).
    for (int s = 1; s < NSTEPS; ++s) {
        const float* src = bufs[s & 1];
        float*       dst = bufs[(s + 1) & 1];
        cudaLaunchKernelEx(&cfg, fk_step, src, dst, out,
                           (const __half2*)dr, dt_days,
                           s / SUBSTEPS, s % SUBSTEPS);
    }

    // Tail for dt==0 batches (fully overlappable).
    cudaLaunchConfig_t tcfg = cfg;
    tcfg.gridDim = dim3(1, W / 4, (W / 4) * BATCH);
    tcfg.blockDim = dim3(32, 4, 4);
    cudaLaunchKernelEx(&tcfg, fk_tail, u_t0, out, dt_days);

    (void)in_sizes; (void)n_in; (void)out_size;
}